// round 3
// baseline (speedup 1.0000x reference)
#include <cuda_runtime.h>
#include <math.h>

#define N_ANGLES 128
#define NCH      1024          // 8 * 128  (c,h) slices
#define NI       16            // feature angle samples
#define WW       128           // detector width
#define PADL     32
#define TABW     192           // padded window

__device__ float g_h[256];                 // doubled ramp taps
__device__ float g_G[NI * NCH * WW];       // 8 MB filtered features

// ---- packed f32x2 helpers (sm_103a) ----
__device__ __forceinline__ unsigned long long pk2(float lo, float hi) {
    unsigned long long r;
    asm("mov.b64 %0, {%1, %2};" : "=l"(r) : "f"(lo), "f"(hi));
    return r;
}
__device__ __forceinline__ void upk2(unsigned long long v, float& lo, float& hi) {
    asm("mov.b64 {%0, %1}, %2;" : "=f"(lo), "=f"(hi) : "l"(v));
}
__device__ __forceinline__ unsigned long long add2(unsigned long long a, unsigned long long b) {
    unsigned long long r;
    asm("add.rn.f32x2 %0, %1, %2;" : "=l"(r) : "l"(a), "l"(b));
    return r;
}
__device__ __forceinline__ unsigned long long fma2(unsigned long long a, unsigned long long b,
                                                   unsigned long long c) {
    unsigned long long r;
    asm("fma.rn.f32x2 %0, %1, %2, %3;" : "=l"(r) : "l"(a), "l"(b), "l"(c));
    return r;
}

// ---------------- K1: ramp taps, parallel (block n, thread k, block-reduce)
__global__ void k_taps() {
    __shared__ float red[4];
    int n = blockIdx.x;
    int k = threadIdx.x;
    float fk = (float)min(k, 128 - k) * (1.0f / 128.0f);
    int m = (k * n) & 127;
    float v = fk * cosf((float)m * 0.049087385212340526f);   // 2*pi/128
    for (int o = 16; o; o >>= 1) v += __shfl_xor_sync(~0u, v, o);
    if ((k & 31) == 0) red[k >> 5] = v;
    __syncthreads();
    if (k == 0) {
        float s = (red[0] + red[1] + red[2] + red[3]) * (1.0f / 128.0f);
        g_h[n] = s;
        g_h[n + 128] = s;
    }
}

// ---------------- K2: G[i][ch][w] = circular conv of feature row with h
__global__ void k_filter(const float* __restrict__ feat) {
    __shared__ float row[128];
    __shared__ float h2[256];
    int b = blockIdx.x;
    int t = threadIdx.x;
    row[t] = feat[b * 128 + t];
    h2[t] = g_h[t];
    h2[t + 128] = g_h[t + 128];
    __syncthreads();
    float acc = 0.0f;
#pragma unroll 8
    for (int wp = 0; wp < 128; wp++)
        acc = fmaf(row[wp], h2[t - wp + 128], acc);
    g_G[b * 128 + t] = acc;
}

// ---------------- K3+K4 fused: table in smem + dual-orientation backprojection
__global__ void __launch_bounds__(512, 1) k_backproj(float* __restrict__ out) {
    extern __shared__ float2 tab[];                 // 128 angles x 192 (q,d)
    __shared__ float  sG[17 * 128];
    __shared__ float2 sc[128];
    int ch  = blockIdx.x;
    int tid = threadIdx.x;
    int lane = tid & 31;
    int wid  = tid >> 5;                 // 0..15
    int xb = (wid >> 2) << 5;            // warp tile: 32x32 pixels
    int yb = (wid & 3) << 5;

    // stage filtered rows (i = 0..16, row 16 wraps to 0)
    for (int k = tid; k < 17 * 128; k += 512) {
        int i = k >> 7;
        int w = k & 127;
        int ig = (i == 16) ? 0 : i;
        sG[k] = g_G[(ig * NCH + ch) * WW + w];
    }
    if (tid < 128) {
        float ang = (float)tid * 0.024543692603601845f;   // pi/128
        float sv, cv;
        sincosf(ang, &sv, &cv);
        sc[tid] = make_float2(cv, sv);
    }
    __syncthreads();

    // build padded (q,d) table, fusing the angle-lerp
    for (int e = tid; e < N_ANGLES * TABW; e += 512) {
        int a  = e / TABW;
        int wq = e - a * TABW;
        int   i0g = a >> 3;
        float wa  = (float)(a & 7) * 0.125f;
        const float* G0 = sG + (i0g << 7);
        int wi = wq - PADL;
        float f0 = 0.0f, f1 = 0.0f;
        if (wi >= 0 && wi < WW)
            f0 = fmaf(G0[wi + 128] - G0[wi], wa, G0[wi]);
        int wi1 = wi + 1;
        if (wi1 >= 0 && wi1 < WW)
            f1 = fmaf(G0[wi1 + 128] - G0[wi1], wa, G0[wi1]);
        tab[e] = make_float2(0.5f * (f0 + f1), f1 - f0);
    }
    __syncthreads();

    const float MAGIC = 12582912.0f;      // 2^23 + 2^22
    const unsigned long long M2   = pk2(MAGIC, MAGIC);
    const unsigned long long NM2  = pk2(-MAGIC, -MAGIC);
    const unsigned long long NEG1 = pk2(-1.0f, -1.0f);

    float accA[32], accB[32];
#pragma unroll
    for (int i = 0; i < 32; i++) { accA[i] = 0.0f; accB[i] = 0.0f; }

    // ---- pass A: |cos| >= |sin|  (a = 96..127, 0..32); lane = y, march x
    {
        float yc = (float)(yb + lane) - 63.5f;
        for (int t = 0; t < 65; t++) {
            int a = (t + 96) & 127;
            float cv = sc[a].x, sv = sc[a].y;
            const float2* row = tab + a * TABW + PADL;
            float ua = fmaf((float)xb - 63.5f, cv, fmaf(yc, sv, 63.0f));
            unsigned long long u2    = pk2(ua, ua + cv);
            unsigned long long step2 = pk2(2.0f * cv, 2.0f * cv);
#pragma unroll
            for (int j = 0; j < 16; j++) {
                unsigned long long m2   = add2(u2, M2);
                unsigned long long i0f2 = add2(m2, NM2);
                unsigned long long fr2  = fma2(i0f2, NEG1, u2);
                u2 = add2(u2, step2);
                float mA, mB, frA, frB;
                upk2(m2, mA, mB);
                upk2(fr2, frA, frB);
                float2 pA = row[__float_as_int(mA) - 0x4B400000];
                float2 pB = row[__float_as_int(mB) - 0x4B400000];
                accA[2 * j]     = fmaf(frA, pA.y, accA[2 * j]     + pA.x);
                accA[2 * j + 1] = fmaf(frB, pB.y, accA[2 * j + 1] + pB.x);
            }
        }
    }

    // ---- pass B: |sin| > |cos|  (a = 33..95); lane = x, march y
    {
        float xc = (float)(xb + lane) - 63.5f;
        for (int a = 33; a < 96; a++) {
            float cv = sc[a].x, sv = sc[a].y;
            const float2* row = tab + a * TABW + PADL;
            float ua = fmaf(xc, cv, fmaf((float)yb - 63.5f, sv, 63.0f));
            unsigned long long u2    = pk2(ua, ua + sv);
            unsigned long long step2 = pk2(2.0f * sv, 2.0f * sv);
#pragma unroll
            for (int j = 0; j < 16; j++) {
                unsigned long long m2   = add2(u2, M2);
                unsigned long long i0f2 = add2(m2, NM2);
                unsigned long long fr2  = fma2(i0f2, NEG1, u2);
                u2 = add2(u2, step2);
                float mA, mB, frA, frB;
                upk2(m2, mA, mB);
                upk2(fr2, frA, frB);
                float2 pA = row[__float_as_int(mA) - 0x4B400000];
                float2 pB = row[__float_as_int(mB) - 0x4B400000];
                accB[2 * j]     = fmaf(frA, pA.y, accB[2 * j]     + pA.x);
                accB[2 * j + 1] = fmaf(frB, pB.y, accB[2 * j + 1] + pB.x);
            }
        }
    }

    // ---- warp-local 32x32 transpose of accB into the A (lane=y) mapping
#pragma unroll
    for (int m = 16; m >= 1; m >>= 1) {
        bool hi = (lane & m) != 0;
#pragma unroll
        for (int i = 0; i < 32; i++) {
            if ((i & m) == 0) {
                int j = i + m;
                float send = hi ? accB[i] : accB[j];
                float recv = __shfl_xor_sync(0xffffffffu, send, m);
                if (hi) accB[i] = recv; else accB[j] = recv;
            }
        }
    }

    // ---- merged store: lane = y (coalesced)
    const float scale = 0.024543692603601845f;        // pi/128
    float* o = out + ch * 16384 + yb + lane;
#pragma unroll
    for (int i = 0; i < 32; i++)
        o[(xb + i) * 128] = (accA[i] + accB[i]) * scale;
}

extern "C" void kernel_launch(void* const* d_in, const int* in_sizes, int n_in,
                              void* d_out, int out_size) {
    const float* feat = (const float*)d_in[0];
    float* out = (float*)d_out;

    cudaFuncSetAttribute(k_backproj, cudaFuncAttributeMaxDynamicSharedMemorySize,
                         N_ANGLES * TABW * (int)sizeof(float2));

    k_taps<<<128, 128>>>();
    k_filter<<<NI * NCH, 128>>>(feat);
    k_backproj<<<NCH, 512, N_ANGLES * TABW * sizeof(float2)>>>(out);
}

// round 6
// speedup vs baseline: 1.7760x; 1.7760x over previous
#include <cuda_runtime.h>
#include <math.h>

#define N_ANGLES 128
#define NCH      1024          // 8 * 128  (c,h) slices
#define NI       16            // feature angle samples
#define WW       128           // detector width
#define PADL     32
#define TABW     192           // padded window

__device__ float g_h[256];                 // doubled ramp taps
__device__ float g_G[NI * NCH * WW];       // 8 MB filtered features

// ---- packed f32x2 helpers (sm_103a) ----
__device__ __forceinline__ unsigned long long pk2(float lo, float hi) {
    unsigned long long r;
    asm("mov.b64 %0, {%1, %2};" : "=l"(r) : "f"(lo), "f"(hi));
    return r;
}
__device__ __forceinline__ void upk2(unsigned long long v, float& lo, float& hi) {
    asm("mov.b64 {%0, %1}, %2;" : "=f"(lo), "=f"(hi) : "l"(v));
}
__device__ __forceinline__ unsigned long long add2(unsigned long long a, unsigned long long b) {
    unsigned long long r;
    asm("add.rn.f32x2 %0, %1, %2;" : "=l"(r) : "l"(a), "l"(b));
    return r;
}
__device__ __forceinline__ unsigned long long fma2(unsigned long long a, unsigned long long b,
                                                   unsigned long long c) {
    unsigned long long r;
    asm("fma.rn.f32x2 %0, %1, %2, %3;" : "=l"(r) : "l"(a), "l"(b), "l"(c));
    return r;
}

// ---------------- K1: ramp taps (block n, thread k, block-reduce)
__global__ void k_taps() {
    __shared__ float red[4];
    int n = blockIdx.x;
    int k = threadIdx.x;
    float fk = (float)min(k, 128 - k) * (1.0f / 128.0f);
    int m = (k * n) & 127;
    float v = fk * cosf((float)m * 0.049087385212340526f);   // 2*pi/128
    for (int o = 16; o; o >>= 1) v += __shfl_xor_sync(~0u, v, o);
    if ((k & 31) == 0) red[k >> 5] = v;
    __syncthreads();
    if (k == 0) {
        float s = (red[0] + red[1] + red[2] + red[3]) * (1.0f / 128.0f);
        g_h[n] = s;
        g_h[n + 128] = s;
    }
}

// ---------------- K2: G[i][ch][w] = circular conv of feature row with h
__global__ void k_filter(const float* __restrict__ feat) {
    __shared__ float row[128];
    __shared__ float h2[256];
    int b = blockIdx.x;
    int t = threadIdx.x;
    row[t] = feat[b * 128 + t];
    h2[t] = g_h[t];
    h2[t + 128] = g_h[t + 128];
    __syncthreads();
    float acc = 0.0f;
#pragma unroll 8
    for (int wp = 0; wp < 128; wp++)
        acc = fmaf(row[wp], h2[t - wp + 128], acc);
    g_G[b * 128 + t] = acc;
}

// ---------------- K3+K4 fused: build (q,d) table in smem, then backproject
// 1024 threads (32 warps) for latency hiding; 16 output elems per thread.
__global__ void __launch_bounds__(1024, 1) k_backproj(float* __restrict__ out) {
    extern __shared__ float2 tab[];                 // 128 angles x 192 (q,d)
    __shared__ float  sG[17 * 128];
    __shared__ float2 sc[128];
    int ch  = blockIdx.x;
    int tid = threadIdx.x;

    // stage filtered rows (i = 0..16, row 16 wraps to 0)
    for (int k = tid; k < 17 * 128; k += 1024) {
        int i = k >> 7;
        int w = k & 127;
        int ig = (i == 16) ? 0 : i;
        sG[k] = g_G[(ig * NCH + ch) * WW + w];
    }
    if (tid < 128) {
        float ang = (float)tid * 0.024543692603601845f;   // pi/128
        float sv, cv;
        sincosf(ang, &sv, &cv);
        sc[tid] = make_float2(cv, sv);
    }
    __syncthreads();

    // build padded (q,d) table, fusing the angle-lerp
    for (int e = tid; e < N_ANGLES * TABW; e += 1024) {
        int a  = e / TABW;
        int wq = e - a * TABW;
        int   i0g = a >> 3;
        float wa  = (float)(a & 7) * 0.125f;
        const float* G0 = sG + (i0g << 7);            // rows i0g, i0g+1 (wrap ok)
        int wi = wq - PADL;
        float f0 = 0.0f, f1 = 0.0f;
        if (wi >= 0 && wi < WW)
            f0 = fmaf(G0[wi + 128] - G0[wi], wa, G0[wi]);
        int wi1 = wi + 1;
        if (wi1 >= 0 && wi1 < WW)
            f1 = fmaf(G0[wi1 + 128] - G0[wi1], wa, G0[wi1]);
        tab[e] = make_float2(0.5f * (f0 + f1), f1 - f0);
    }
    __syncthreads();

    int l     = tid & 31;
    int wid   = tid >> 5;                 // 0..31
    int y     = ((wid & 3) << 5) + l;     // lanes = consecutive y
    float yc  = (float)y - 63.5f;
    int xbase = wid >> 2;                 // 0..7 ; thread covers x = xbase + 8*i

    float acc[16];
#pragma unroll
    for (int i = 0; i < 16; i++) acc[i] = 0.0f;

    const float MAGIC = 12582912.0f;      // 2^23 + 2^22
    const unsigned long long M2   = pk2(MAGIC, MAGIC);
    const unsigned long long NM2  = pk2(-MAGIC, -MAGIC);
    const unsigned long long NEG1 = pk2(-1.0f, -1.0f);

    for (int a = 0; a < N_ANGLES; a++) {
        float cv = sc[a].x, sv = sc[a].y;
        const float2* row = tab + a * TABW + PADL;
        // u' = u - 0.5 = xc*cos + yc*sin + 63.0
        float ua = fmaf((float)xbase - 63.5f, cv, fmaf(yc, sv, 63.0f));
        float ub = fmaf(8.0f, cv, ua);
        unsigned long long u2    = pk2(ua, ub);
        unsigned long long step2 = pk2(16.0f * cv, 16.0f * cv);
#pragma unroll
        for (int j = 0; j < 8; j++) {
            unsigned long long m2   = add2(u2, M2);        // round into mantissa
            unsigned long long i0f2 = add2(m2, NM2);       // rni(u') as float
            unsigned long long fr2  = fma2(i0f2, NEG1, u2);// u' - rni(u') in [-.5,.5]
            u2 = add2(u2, step2);

            float mA, mB, frA, frB;
            upk2(m2, mA, mB);
            upk2(fr2, frA, frB);
            float2 pA = row[__float_as_int(mA) - 0x4B400000];  // LDS.64 (q,d)
            float2 pB = row[__float_as_int(mB) - 0x4B400000];
            acc[2 * j]     = fmaf(frA, pA.y, acc[2 * j]     + pA.x);
            acc[2 * j + 1] = fmaf(frB, pB.y, acc[2 * j + 1] + pB.x);
        }
    }

    const float scale = 0.024543692603601845f;        // pi/128
    float* o = out + ch * 16384 + y;
#pragma unroll
    for (int i = 0; i < 16; i++) {
        int x = xbase + 8 * i;
        o[x * 128] = acc[i] * scale;                  // coalesced across lanes (y)
    }
}

extern "C" void kernel_launch(void* const* d_in, const int* in_sizes, int n_in,
                              void* d_out, int out_size) {
    const float* feat = (const float*)d_in[0];
    float* out = (float*)d_out;

    cudaFuncSetAttribute(k_backproj, cudaFuncAttributeMaxDynamicSharedMemorySize,
                         N_ANGLES * TABW * (int)sizeof(float2));

    k_taps<<<128, 128>>>();
    k_filter<<<NI * NCH, 128>>>(feat);
    k_backproj<<<NCH, 1024, N_ANGLES * TABW * sizeof(float2)>>>(out);
}

// round 17
// speedup vs baseline: 1.8116x; 1.0201x over previous
#include <cuda_runtime.h>
#include <math.h>

#define N_ANGLES 128
#define NCH      1024          // 8 * 128  (c,h) slices
#define NI       16            // feature angle samples
#define WW       128           // detector width
#define PADL     32
#define TABW     192           // padded window

__device__ float g_h[256];     // doubled ramp taps

// ---- packed f32x2 helpers (sm_103a) ----
__device__ __forceinline__ unsigned long long pk2(float lo, float hi) {
    unsigned long long r;
    asm("mov.b64 %0, {%1, %2};" : "=l"(r) : "f"(lo), "f"(hi));
    return r;
}
__device__ __forceinline__ void upk2(unsigned long long v, float& lo, float& hi) {
    asm("mov.b64 {%0, %1}, %2;" : "=f"(lo), "=f"(hi) : "l"(v));
}
__device__ __forceinline__ unsigned long long add2(unsigned long long a, unsigned long long b) {
    unsigned long long r;
    asm("add.rn.f32x2 %0, %1, %2;" : "=l"(r) : "l"(a), "l"(b));
    return r;
}

// ---------------- K1: ramp taps (block n, thread k, block-reduce)
__global__ void k_taps() {
    __shared__ float red[4];
    int n = blockIdx.x;
    int k = threadIdx.x;
    float fk = (float)min(k, 128 - k) * (1.0f / 128.0f);
    int m = (k * n) & 127;
    float v = fk * cosf((float)m * 0.049087385212340526f);   // 2*pi/128
    for (int o = 16; o; o >>= 1) v += __shfl_xor_sync(~0u, v, o);
    if ((k & 31) == 0) red[k >> 5] = v;
    __syncthreads();
    if (k == 0) {
        float s = (red[0] + red[1] + red[2] + red[3]) * (1.0f / 128.0f);
        g_h[n] = s;
        g_h[n + 128] = s;
    }
}

// ---------------- Fused: filter + table build + backprojection
// 1024 threads (32 warps); 16 output elems per thread.
// Table is pre-linearized: entry i holds (e, d) with e = q - i*d, so the
// bilinear sample is  val = e[i0] + u' * d[i0]  with i0 = rni(u') — no frac.
__global__ void __launch_bounds__(1024, 1) k_backproj(const float* __restrict__ feat,
                                                      float* __restrict__ out) {
    extern __shared__ float2 tab[];                 // 128 angles x 192 (e,d)
    __shared__ float  sG[17 * 128];                 // filtered rows
    __shared__ float  sh[256];                      // taps (doubled)
    __shared__ float2 sc[128];                      // (cos, sin)
    int ch  = blockIdx.x;
    int tid = threadIdx.x;

    // Phase 0: stage raw feature rows into tab's memory (dead until table build)
    float* sF = (float*)tab;                        // 17*128 floats
    for (int k = tid; k < 17 * 128; k += 1024) {
        int i = k >> 7;
        int w = k & 127;
        int ig = (i == 16) ? 0 : i;
        sF[k] = feat[(ig * NCH + ch) * WW + w];
    }
    if (tid < 256) sh[tid] = g_h[tid];
    if (tid < 128) {
        float ang = (float)tid * 0.024543692603601845f;   // pi/128
        float sv, cv;
        sincosf(ang, &sv, &cv);
        sc[tid] = make_float2(cv, sv);
    }
    __syncthreads();

    // Phase 1: circular conv of each staged row with the ramp taps
    for (int k = tid; k < 17 * 128; k += 1024) {
        int rb = k & ~127;                          // row base
        int t  = k & 127;
        const float* rowF = sF + rb;
        float acc = 0.0f;
#pragma unroll 8
        for (int w = 0; w < 128; w++)
            acc = fmaf(rowF[w], sh[t - w + 128], acc);
        sG[k] = acc;
    }
    __syncthreads();

    // Phase 2: build padded (e,d) table, fusing the angle-lerp (overwrites sF)
    for (int eidx = tid; eidx < N_ANGLES * TABW; eidx += 1024) {
        int a  = eidx / TABW;
        int wq = eidx - a * TABW;
        int   i0g = a >> 3;
        float wa  = (float)(a & 7) * 0.125f;
        const float* G0 = sG + (i0g << 7);          // rows i0g, i0g+1 (wrap ok)
        int wi = wq - PADL;
        float f0 = 0.0f, f1 = 0.0f;
        if (wi >= 0 && wi < WW)
            f0 = fmaf(G0[wi + 128] - G0[wi], wa, G0[wi]);
        int wi1 = wi + 1;
        if (wi1 >= 0 && wi1 < WW)
            f1 = fmaf(G0[wi1 + 128] - G0[wi1], wa, G0[wi1]);
        float dd = f1 - f0;
        float q  = 0.5f * (f0 + f1);
        tab[eidx] = make_float2(fmaf(-(float)wi, dd, q), dd);   // (e, d)
    }
    __syncthreads();

    // Phase 3: backprojection mainloop
    int l     = tid & 31;
    int wid   = tid >> 5;                 // 0..31
    int y     = ((wid & 3) << 5) + l;     // lanes = consecutive y
    float yc  = (float)y - 63.5f;
    int xbase = wid >> 2;                 // 0..7 ; thread covers x = xbase + 8*i

    float acc[16];
#pragma unroll
    for (int i = 0; i < 16; i++) acc[i] = 0.0f;

    const float MAGIC = 12582912.0f;      // 2^23 + 2^22
    const unsigned long long M2 = pk2(MAGIC, MAGIC);

    for (int a = 0; a < N_ANGLES; a++) {
        float cv = sc[a].x, sv = sc[a].y;
        const float2* row = tab + a * TABW + PADL;
        // u' = u - 0.5 = xc*cos + yc*sin + 63.0
        float ua = fmaf((float)xbase - 63.5f, cv, fmaf(yc, sv, 63.0f));
        float ub = fmaf(8.0f, cv, ua);
        unsigned long long u2    = pk2(ua, ub);
        unsigned long long step2 = pk2(16.0f * cv, 16.0f * cv);
#pragma unroll
        for (int j = 0; j < 8; j++) {
            unsigned long long m2 = add2(u2, M2);   // i0 = rni(u') in mantissa
            float mA, mB, uA, uB;
            upk2(m2, mA, mB);
            upk2(u2, uA, uB);                       // register-half reads (elide)
            float2 pA = row[__float_as_int(mA) - 0x4B400000];  // LDS.64 (e,d)
            float2 pB = row[__float_as_int(mB) - 0x4B400000];
            acc[2 * j]     = fmaf(uA, pA.y, acc[2 * j]     + pA.x);
            acc[2 * j + 1] = fmaf(uB, pB.y, acc[2 * j + 1] + pB.x);
            u2 = add2(u2, step2);
        }
    }

    const float scale = 0.024543692603601845f;        // pi/128
    float* o = out + ch * 16384 + y;
#pragma unroll
    for (int i = 0; i < 16; i++) {
        int x = xbase + 8 * i;
        o[x * 128] = acc[i] * scale;                  // coalesced across lanes (y)
    }
}

extern "C" void kernel_launch(void* const* d_in, const int* in_sizes, int n_in,
                              void* d_out, int out_size) {
    const float* feat = (const float*)d_in[0];
    float* out = (float*)d_out;

    cudaFuncSetAttribute(k_backproj, cudaFuncAttributeMaxDynamicSharedMemorySize,
                         N_ANGLES * TABW * (int)sizeof(float2));

    k_taps<<<128, 128>>>();
    k_backproj<<<NCH, 1024, N_ANGLES * TABW * sizeof(float2)>>>(feat, out);
}